// round 6
// baseline (speedup 1.0000x reference)
#include <cuda_runtime.h>
#include <cstdint>

// ---------------- problem constants ----------------
#define BB    32
#define PP    14
#define CC    768
#define HH    12
#define HD    64
#define HIDN  3072
#define NWIN  49
#define NPIX  196          // 14*14
#define ROWS  6272         // 32*196

// ---------------- scratch (static device globals; no allocation) ----------------
__device__ float g_xin  [(size_t)ROWS * CC];
__device__ float g_qkv  [(size_t)ROWS * 3 * CC];
__device__ float g_attn [(size_t)ROWS * CC];
__device__ float g_xattn[(size_t)ROWS * CC];
__device__ float g_h1   [(size_t)ROWS * HIDN];
__device__ float g_h2   [(size_t)ROWS * HIDN];
__device__ float g_h3   [(size_t)ROWS * CC];
__device__ float g_s1   [HIDN];
__device__ float g_s2   [HIDN];
__device__ float g_semean [BB * HIDN];
__device__ float g_sescale[BB * HIDN];

__device__ __forceinline__ int reg3(int r) { return r < 7 ? 0 : (r < 11 ? 1 : 2); }

// ---------------- cls passthrough ----------------
__global__ void k_cls(const float* __restrict__ x, float* __restrict__ out) {
    int i = blockIdx.x * blockDim.x + threadIdx.x;
    if (i >= BB * CC) return;
    int b = i / CC, c = i % CC;
    out[(size_t)b * 197 * CC + c] = x[(size_t)b * 197 * CC + c];
}

// ---------------- copy pixel tokens (drop cls) ----------------
__global__ void k_copyx(const float* __restrict__ x) {
    int i = blockIdx.x * blockDim.x + threadIdx.x;
    if (i >= ROWS * (CC / 4)) return;
    int c4  = i % (CC / 4);
    int row = i / (CC / 4);
    int b = row / NPIX, p = row % NPIX;
    float4 v = *(const float4*)(x + ((size_t)b * 197 + 1 + p) * CC + c4 * 4);
    *(float4*)(g_xin + (size_t)row * CC + c4 * 4) = v;
}

// ---------------- SGEMM: C[M,N] = A[M,K] @ W[N,K]^T ----------------
template <int MODE>
__device__ __forceinline__ void sgemm_body(
    const float* __restrict__ A, const float* __restrict__ W, float* __restrict__ Cmat,
    int N, int K, const float* __restrict__ bias, const float* __restrict__ ascale)
{
    __shared__ float As[8][128];
    __shared__ float Bs[8][128];

    const int tid = threadIdx.x;
    const int tx = tid & 15, ty = tid >> 4;
    const int mBase = blockIdx.y * 128;
    const int nBase = blockIdx.x * 128;
    const int loadRow = tid >> 1;
    const int loadCol = (tid & 1) * 4;

    float acc[8][8];
#pragma unroll
    for (int i = 0; i < 8; i++)
#pragma unroll
        for (int j = 0; j < 8; j++) acc[i][j] = 0.f;

    const int aRow = mBase + loadRow;
    const int wRow = nBase + loadRow;
    const int bofs = (MODE == 2) ? (aRow / NPIX) * HIDN : 0;

    for (int k0 = 0; k0 < K; k0 += 8) {
        float4 a4 = *(const float4*)(A + (size_t)aRow * K + k0 + loadCol);
        if (MODE == 2) {
            float4 s4 = *(const float4*)(ascale + bofs + k0 + loadCol);
            a4.x *= s4.x; a4.y *= s4.y; a4.z *= s4.z; a4.w *= s4.w;
        }
        float4 w4 = *(const float4*)(W + (size_t)wRow * K + k0 + loadCol);
        As[loadCol + 0][loadRow] = a4.x;
        As[loadCol + 1][loadRow] = a4.y;
        As[loadCol + 2][loadRow] = a4.z;
        As[loadCol + 3][loadRow] = a4.w;
        Bs[loadCol + 0][loadRow] = w4.x;
        Bs[loadCol + 1][loadRow] = w4.y;
        Bs[loadCol + 2][loadRow] = w4.z;
        Bs[loadCol + 3][loadRow] = w4.w;
        __syncthreads();
#pragma unroll
        for (int kk = 0; kk < 8; kk++) {
            float ar[8], br[8];
            float4 t;
            t = *(float4*)&As[kk][ty * 8];     ar[0]=t.x; ar[1]=t.y; ar[2]=t.z; ar[3]=t.w;
            t = *(float4*)&As[kk][ty * 8 + 4]; ar[4]=t.x; ar[5]=t.y; ar[6]=t.z; ar[7]=t.w;
            t = *(float4*)&Bs[kk][tx * 8];     br[0]=t.x; br[1]=t.y; br[2]=t.z; br[3]=t.w;
            t = *(float4*)&Bs[kk][tx * 8 + 4]; br[4]=t.x; br[5]=t.y; br[6]=t.z; br[7]=t.w;
#pragma unroll
            for (int i = 0; i < 8; i++)
#pragma unroll
                for (int j = 0; j < 8; j++) acc[i][j] += ar[i] * br[j];
        }
        __syncthreads();
    }

#pragma unroll
    for (int i = 0; i < 8; i++) {
        int gm = mBase + ty * 8 + i;
        float* dst = Cmat + (size_t)gm * N + nBase + tx * 8;
#pragma unroll
        for (int j = 0; j < 8; j += 4) {
            float4 v;
            v.x = acc[i][j + 0]; v.y = acc[i][j + 1];
            v.z = acc[i][j + 2]; v.w = acc[i][j + 3];
            if (MODE == 1) {
                const float* bp = bias + nBase + tx * 8 + j;
                v.x += bp[0]; v.y += bp[1]; v.z += bp[2]; v.w += bp[3];
            }
            *(float4*)(dst + j) = v;
        }
    }
}

__global__ __launch_bounds__(256) void k_gemm_qkv(const float* __restrict__ W) {
    sgemm_body<0>(g_xin, W, g_qkv, 3 * CC, CC, nullptr, nullptr);
}
__global__ __launch_bounds__(256) void k_gemm_proj(const float* __restrict__ W, const float* __restrict__ bias) {
    sgemm_body<1>(g_attn, W, g_xattn, CC, CC, bias, nullptr);
}
__global__ __launch_bounds__(256) void k_gemm_pw1(const float* __restrict__ W) {
    sgemm_body<0>(g_xattn, W, g_h1, HIDN, CC, nullptr, nullptr);
}
__global__ __launch_bounds__(256) void k_gemm_pw2(const float* __restrict__ W) {
    sgemm_body<2>(g_h2, W, g_h3, CC, HIDN, nullptr, g_sescale);
}

// ---------------- fused window attention ----------------
__global__ __launch_bounds__(256) void k_attn(const float* __restrict__ rpb) {
    __shared__ float qs[NWIN * HD];
    __shared__ float ks[NWIN * HD];
    __shared__ float vs[NWIN * HD];
    __shared__ float sc[NWIN * 50];
    __shared__ int   prow[NWIN];
    __shared__ int   lab [NWIN];

    const int bw = blockIdx.x;     // b*4 + w, w = wrow*2 + wcol
    const int h  = blockIdx.y;
    const int tid = threadIdx.x;

    const int b = bw >> 2, w = bw & 3;

    if (tid < NWIN) {
        int rr = (w >> 1) * 7 + tid / 7;     // rolled-image row
        int cc = (w & 1) * 7 + tid % 7;      // rolled-image col
        prow[tid] = b * NPIX + ((rr + 3) % 14) * 14 + ((cc + 3) % 14);
        lab[tid]  = reg3(rr) * 3 + reg3(cc);
    }
    __syncthreads();

    for (int idx = tid; idx < NWIN * HD; idx += 256) {
        int t = idx >> 6, d = idx & 63;
        const float* base = g_qkv + (size_t)prow[t] * (3 * CC) + h * HD + d;
        qs[idx] = base[0];
        ks[idx] = base[CC];
        vs[idx] = base[2 * CC];
    }
    __syncthreads();

    for (int s = tid; s < NWIN * NWIN; s += 256) {
        int qi = s / NWIN, ki = s % NWIN;
        float a = 0.f;
#pragma unroll
        for (int d = 0; d < HD; d++) a += qs[qi * HD + d] * ks[ki * HD + d];
        a *= 0.125f;
        int qr = qi / 7, qc = qi % 7, kr = ki / 7, kc = ki % 7;
        int rpi = (qr - kr + 6) * 13 + (qc - kc + 6);
        a += rpb[rpi * HH + h];
        if (lab[qi] != lab[ki]) a -= 100.f;
        sc[qi * 50 + ki] = a;
    }
    __syncthreads();

    if (tid < NWIN) {
        float m = -1e30f;
        for (int k = 0; k < NWIN; k++) m = fmaxf(m, sc[tid * 50 + k]);
        float sum = 0.f;
        for (int k = 0; k < NWIN; k++) {
            float e = expf(sc[tid * 50 + k] - m);
            sc[tid * 50 + k] = e; sum += e;
        }
        float inv = 1.f / sum;
        for (int k = 0; k < NWIN; k++) sc[tid * 50 + k] *= inv;
    }
    __syncthreads();

    for (int idx = tid; idx < NWIN * HD; idx += 256) {
        int qi = idx >> 6, d = idx & 63;
        float a = 0.f;
#pragma unroll
        for (int k = 0; k < NWIN; k++) a += sc[qi * 50 + k] * vs[k * HD + d];
        g_attn[(size_t)prow[qi] * CC + h * HD + d] = a;
    }
}

// ---------------- BN stats ----------------
// NOTE: buffers selected by template param INSIDE device code — passing a
// __device__ global as a host-side kernel argument silently reads the host
// shadow symbol via ATS on GB300 (the R1-R4 bug).
__global__ void k_zero_stats() {
    int i = blockIdx.x * blockDim.x + threadIdx.x;
    if (i < HIDN) { g_s1[i] = 0.f; g_s2[i] = 0.f; }
}

template <int WHICH>
__global__ void k_colstats(int N) {
    const float* __restrict__ h = (WHICH == 0) ? g_h1 : (WHICH == 1) ? g_h2 : g_h3;
    int ch = blockIdx.x * 128 + threadIdx.x;
    int r0 = blockIdx.y * 128;
    float s = 0.f, q = 0.f;
    for (int r = 0; r < 128; r++) {
        float v = h[(size_t)(r0 + r) * N + ch];
        s += v; q += v * v;
    }
    atomicAdd(&g_s1[ch], s);
    atomicAdd(&g_s2[ch], q);
}

// ---------------- BN + hardswish (in place) ----------------
template <int WHICH>
__global__ void k_bn_hswish(int N, const float* __restrict__ g, const float* __restrict__ b) {
    float* h = (WHICH == 0) ? g_h1 : g_h2;
    int i = blockIdx.x * blockDim.x + threadIdx.x;
    if (i >= ROWS * (N / 4)) return;
    int c4 = (i % (N / 4)) * 4;
    float4 v = *(float4*)(h + (size_t)i * 4);
    float vv[4] = { v.x, v.y, v.z, v.w };
#pragma unroll
    for (int j = 0; j < 4; j++) {
        int ch = c4 + j;
        float m   = g_s1[ch] * (1.f / ROWS);
        float var = fmaxf(g_s2[ch] * (1.f / ROWS) - m * m, 0.f);
        float x = (vv[j] - m) * rsqrtf(var + 1e-5f) * g[ch] + b[ch];
        vv[j] = x * fminf(fmaxf(x + 3.f, 0.f), 6.f) * (1.f / 6.f);
    }
    *(float4*)(h + (size_t)i * 4) = make_float4(vv[0], vv[1], vv[2], vv[3]);
}

// ---------------- depthwise 3x3 (NHWC, zero 'SAME' padding) ----------------
__global__ void k_dwconv(const float* __restrict__ w) {
    int i = blockIdx.x * blockDim.x + threadIdx.x;
    if (i >= ROWS * (HIDN / 4)) return;
    int c4  = i % (HIDN / 4);
    int pix = i / (HIDN / 4);
    int b = pix / NPIX, p = pix % NPIX;
    int r = p / 14, c = p % 14;

    float wt[4][9];
#pragma unroll
    for (int j = 0; j < 4; j++)
#pragma unroll
        for (int t = 0; t < 9; t++) wt[j][t] = w[(size_t)(c4 * 4 + j) * 9 + t];

    float acc[4] = {0.f, 0.f, 0.f, 0.f};
#pragma unroll
    for (int dr = 0; dr < 3; dr++) {
        int rr = r + dr - 1;
        if (rr < 0 || rr > 13) continue;
#pragma unroll
        for (int dc = 0; dc < 3; dc++) {
            int cc = c + dc - 1;
            if (cc < 0 || cc > 13) continue;
            float4 v = *(const float4*)(g_h1 + ((size_t)(b * NPIX + rr * 14 + cc)) * HIDN + c4 * 4);
            acc[0] += v.x * wt[0][dr * 3 + dc];
            acc[1] += v.y * wt[1][dr * 3 + dc];
            acc[2] += v.z * wt[2][dr * 3 + dc];
            acc[3] += v.w * wt[3][dr * 3 + dc];
        }
    }
    *(float4*)(g_h2 + (size_t)i * 4) = make_float4(acc[0], acc[1], acc[2], acc[3]);
}

// ---------------- SE: pool + MLP ----------------
__global__ void k_sepool() {
    int b  = blockIdx.x;
    int ch = blockIdx.y * 128 + threadIdx.x;
    float s = 0.f;
    for (int p = 0; p < NPIX; p++) s += g_h2[((size_t)b * NPIX + p) * HIDN + ch];
    g_semean[b * HIDN + ch] = s * (1.f / NPIX);
}

__global__ __launch_bounds__(256) void k_semlp(
    const float* __restrict__ w1, const float* __restrict__ b1,
    const float* __restrict__ w2, const float* __restrict__ b2)
{
    __shared__ float sm[HIDN];
    __shared__ float hid[CC];
    int b = blockIdx.x, tid = threadIdx.x;
    for (int i = tid; i < HIDN; i += 256) sm[i] = g_semean[b * HIDN + i];
    __syncthreads();
    for (int j = tid; j < CC; j += 256) {
        float a = b1[j];
        const float* wr = w1 + (size_t)j * HIDN;
        for (int k = 0; k < HIDN; k += 4) {
            float4 wv = *(const float4*)(wr + k);
            a += wv.x * sm[k] + wv.y * sm[k + 1] + wv.z * sm[k + 2] + wv.w * sm[k + 3];
        }
        hid[j] = fmaxf(a, 0.f);
    }
    __syncthreads();
    for (int o = tid; o < HIDN; o += 256) {
        float a = b2[o];
        const float* wr = w2 + (size_t)o * CC;
        for (int k = 0; k < CC; k += 4) {
            float4 wv = *(const float4*)(wr + k);
            a += wv.x * hid[k] + wv.y * hid[k + 1] + wv.z * hid[k + 2] + wv.w * hid[k + 3];
        }
        g_sescale[b * HIDN + o] = fminf(fmaxf(a + 3.f, 0.f), 6.f) * (1.f / 6.f);
    }
}

// ---------------- final: bn3 + residual + write out ----------------
__global__ void k_final(const float* __restrict__ g, const float* __restrict__ bb,
                        float* __restrict__ out) {
    int i = blockIdx.x * blockDim.x + threadIdx.x;
    if (i >= ROWS * (CC / 4)) return;
    int c4  = (i % (CC / 4)) * 4;
    int pix = i / (CC / 4);
    int b = pix / NPIX, p = pix % NPIX;
    float4 hv = *(float4*)(g_h3 + (size_t)i * 4);
    float4 xv = *(float4*)(g_xattn + (size_t)i * 4);
    float h[4] = { hv.x, hv.y, hv.z, hv.w };
    float x[4] = { xv.x, xv.y, xv.z, xv.w };
#pragma unroll
    for (int j = 0; j < 4; j++) {
        int ch = c4 + j;
        float m   = g_s1[ch] * (1.f / ROWS);
        float var = fmaxf(g_s2[ch] * (1.f / ROWS) - m * m, 0.f);
        x[j] += (h[j] - m) * rsqrtf(var + 1e-5f) * g[ch] + bb[ch];
    }
    float* dst = out + ((size_t)b * 197 + 1 + p) * CC + c4;
    *(float4*)dst = make_float4(x[0], x[1], x[2], x[3]);
}

// ---------------- launch ----------------
extern "C" void kernel_launch(void* const* d_in, const int* in_sizes, int n_in,
                              void* d_out, int out_size) {
    // Input-order dispatch (insertion order default, alphabetical fallback).
    int idx[18];
    for (int i = 0; i < 18; i++) idx[i] = i;
    const int X_ELEMS = BB * 197 * CC;
    if (n_in == 18 && in_sizes[0] != X_ELEMS && in_sizes[17] == X_ELEMS) {
        const int m[18] = {17, 16, 15, 0, 10, 8, 2, 1, 7, 4, 3, 13, 11, 14, 12, 9, 6, 5};
        for (int i = 0; i < 18; i++) idx[i] = m[i];
    }

    const float* x      = (const float*)d_in[idx[0]];
    const float* w_qkv  = (const float*)d_in[idx[1]];
    const float* w_proj = (const float*)d_in[idx[2]];
    const float* b_proj = (const float*)d_in[idx[3]];
    const float* rpb    = (const float*)d_in[idx[4]];
    const float* pw1_w  = (const float*)d_in[idx[5]];
    const float* bn1_g  = (const float*)d_in[idx[6]];
    const float* bn1_b  = (const float*)d_in[idx[7]];
    const float* dw_w   = (const float*)d_in[idx[8]];
    const float* bn2_g  = (const float*)d_in[idx[9]];
    const float* bn2_b  = (const float*)d_in[idx[10]];
    const float* se_w1  = (const float*)d_in[idx[11]];
    const float* se_b1  = (const float*)d_in[idx[12]];
    const float* se_w2  = (const float*)d_in[idx[13]];
    const float* se_b2  = (const float*)d_in[idx[14]];
    const float* pw2_w  = (const float*)d_in[idx[15]];
    const float* bn3_g  = (const float*)d_in[idx[16]];
    const float* bn3_b  = (const float*)d_in[idx[17]];
    float* out = (float*)d_out;

    k_cls<<<(BB * CC + 255) / 256, 256>>>(x, out);
    k_copyx<<<(ROWS * (CC / 4) + 255) / 256, 256>>>(x);

    k_gemm_qkv<<<dim3(3 * CC / 128, ROWS / 128), 256>>>(w_qkv);
    k_attn<<<dim3(BB * 4, HH), 256>>>(rpb);
    k_gemm_proj<<<dim3(CC / 128, ROWS / 128), 256>>>(w_proj, b_proj);

    k_gemm_pw1<<<dim3(HIDN / 128, ROWS / 128), 256>>>(pw1_w);
    k_zero_stats<<<(HIDN + 255) / 256, 256>>>();
    k_colstats<0><<<dim3(HIDN / 128, ROWS / 128), 128>>>(HIDN);
    k_bn_hswish<0><<<(ROWS * (HIDN / 4) + 255) / 256, 256>>>(HIDN, bn1_g, bn1_b);

    k_dwconv<<<(ROWS * (HIDN / 4) + 255) / 256, 256>>>(dw_w);
    k_zero_stats<<<(HIDN + 255) / 256, 256>>>();
    k_colstats<1><<<dim3(HIDN / 128, ROWS / 128), 128>>>(HIDN);
    k_bn_hswish<1><<<(ROWS * (HIDN / 4) + 255) / 256, 256>>>(HIDN, bn2_g, bn2_b);

    k_sepool<<<dim3(BB, HIDN / 128), 128>>>();
    k_semlp<<<BB, 256>>>(se_w1, se_b1, se_w2, se_b2);

    k_gemm_pw2<<<dim3(CC / 128, ROWS / 128), 256>>>(pw2_w);
    k_zero_stats<<<(HIDN + 255) / 256, 256>>>();
    k_colstats<2><<<dim3(CC / 128, ROWS / 128), 128>>>(CC);
    k_final<<<(ROWS * (CC / 4) + 255) / 256, 256>>>(bn3_g, bn3_b, out);
    (void)in_sizes; (void)n_in; (void)out_size;
}

// round 8
// speedup vs baseline: 1.5420x; 1.5420x over previous
#include <cuda_runtime.h>
#include <cuda_bf16.h>
#include <cstdint>

// ---------------- problem constants ----------------
#define BB    32
#define PP    14
#define CC    768
#define HH    12
#define HD    64
#define HIDN  3072
#define NWIN  49
#define NPIX  196
#define ROWS  6272         // 32*196

// ---------------- scratch (static device globals; no allocation) ----------------
__device__ float g_xin  [(size_t)ROWS * CC];
__device__ float g_qkv  [(size_t)ROWS * 3 * CC];
__device__ float g_attn [(size_t)ROWS * CC];
__device__ float g_xattn[(size_t)ROWS * CC];
__device__ float g_h1   [(size_t)ROWS * HIDN];
__device__ float g_h2   [(size_t)ROWS * HIDN];
__device__ float g_h3   [(size_t)ROWS * CC];
__device__ float g_s1   [HIDN];
__device__ float g_s2   [HIDN];
__device__ float g_semean [BB * HIDN];
__device__ float g_sescale[BB * HIDN];
// bf16 split scratch
__device__ __nv_bfloat16 g_ahi[(size_t)ROWS * HIDN];
__device__ __nv_bfloat16 g_alo[(size_t)ROWS * HIDN];
__device__ __nv_bfloat16 g_whi[(size_t)HIDN * CC];
__device__ __nv_bfloat16 g_wlo[(size_t)HIDN * CC];

__device__ __forceinline__ int reg3(int r) { return r < 7 ? 0 : (r < 11 ? 1 : 2); }

__device__ __forceinline__ uint32_t s2u(const void* p) {
    uint32_t a;
    asm("{ .reg .u64 t; cvta.to.shared.u64 t, %1; cvt.u32.u64 %0, t; }" : "=r"(a) : "l"(p));
    return a;
}
#define CPA16(dst, src) asm volatile("cp.async.cg.shared.global [%0], [%1], 16;" :: "r"(dst), "l"(src) : "memory")
#define CPA_COMMIT()    asm volatile("cp.async.commit_group;" ::: "memory")
#define CPA_WAIT1()     asm volatile("cp.async.wait_group 1;" ::: "memory")
#define CPA_WAIT0()     asm volatile("cp.async.wait_group 0;" ::: "memory")

__device__ __forceinline__ void ldmA(uint32_t* r, uint32_t addr) {
    asm volatile("ldmatrix.sync.aligned.m8n8.x4.shared.b16 {%0,%1,%2,%3}, [%4];"
                 : "=r"(r[0]), "=r"(r[1]), "=r"(r[2]), "=r"(r[3]) : "r"(addr));
}
__device__ __forceinline__ void ldmB(uint32_t* r, uint32_t addr) {
    asm volatile("ldmatrix.sync.aligned.m8n8.x2.shared.b16 {%0,%1}, [%2];"
                 : "=r"(r[0]), "=r"(r[1]) : "r"(addr));
}
__device__ __forceinline__ void mma16816(float* c, const uint32_t* a, const uint32_t* b) {
    asm volatile("mma.sync.aligned.m16n8k16.row.col.f32.bf16.bf16.f32 "
                 "{%0,%1,%2,%3}, {%4,%5,%6,%7}, {%8,%9}, {%0,%1,%2,%3};"
                 : "+f"(c[0]), "+f"(c[1]), "+f"(c[2]), "+f"(c[3])
                 : "r"(a[0]), "r"(a[1]), "r"(a[2]), "r"(a[3]), "r"(b[0]), "r"(b[1]));
}

// ---------------- cls passthrough ----------------
__global__ void k_cls(const float* __restrict__ x, float* __restrict__ out) {
    int i = blockIdx.x * blockDim.x + threadIdx.x;
    if (i >= BB * CC) return;
    int b = i / CC, c = i % CC;
    out[(size_t)b * 197 * CC + c] = x[(size_t)b * 197 * CC + c];
}

// ---------------- copy pixel tokens (drop cls) ----------------
__global__ void k_copyx(const float* __restrict__ x) {
    int i = blockIdx.x * blockDim.x + threadIdx.x;
    if (i >= ROWS * (CC / 4)) return;
    int c4  = i % (CC / 4);
    int row = i / (CC / 4);
    int b = row / NPIX, p = row % NPIX;
    float4 v = *(const float4*)(x + ((size_t)b * 197 + 1 + p) * CC + c4 * 4);
    *(float4*)(g_xin + (size_t)row * CC + c4 * 4) = v;
}

// ---------------- fp32 -> bf16 (hi,lo) split conversions ----------------
template <int SRC>   // 0:g_xin  1:g_attn  2:g_xattn
__global__ void k_cvt_a(int K) {
    size_t i = (size_t)blockIdx.x * blockDim.x + threadIdx.x;
    if (i >= (size_t)ROWS * K) return;
    const float* src = (SRC == 0) ? g_xin : (SRC == 1) ? g_attn : g_xattn;
    float x = src[i];
    __nv_bfloat16 h = __float2bfloat16(x);
    g_ahi[i] = h;
    g_alo[i] = __float2bfloat16(x - __bfloat162float(h));
}
__global__ void k_cvt_a_se() {
    size_t i = (size_t)blockIdx.x * blockDim.x + threadIdx.x;
    if (i >= (size_t)ROWS * HIDN) return;
    int k = (int)(i % HIDN);
    int b = (int)(i / ((size_t)NPIX * HIDN));
    float x = g_h2[i] * g_sescale[b * HIDN + k];
    __nv_bfloat16 h = __float2bfloat16(x);
    g_ahi[i] = h;
    g_alo[i] = __float2bfloat16(x - __bfloat162float(h));
}
__global__ void k_cvt_w(const float* __restrict__ w, int total) {
    int i = blockIdx.x * blockDim.x + threadIdx.x;
    if (i >= total) return;
    float x = w[i];
    __nv_bfloat16 h = __float2bfloat16(x);
    g_whi[i] = h;
    g_wlo[i] = __float2bfloat16(x - __bfloat162float(h));
}

// ---------------- HMMA GEMM: C[M,N] = A[M,K] @ W[N,K]^T (bf16 3-pass split) ---
// 128x128 CTA tile, BK=32, 8 warps (2x4), warp tile 64x32.
// smem tiles [128][40] bf16 (80B row stride), 2-stage cp.async pipeline.
// MODE: 0:g_qkv 1:g_xattn(+bias) 2:g_h1 3:g_h3
#define TS   40                    // padded row stride (bf16 elems)
#define TILE (128 * TS)            // 5120 elems per tile
#define STG  (4 * TILE)            // 20480 elems per stage
#define GSMEM (2 * STG * 2)        // bytes: 81920

template <int MODE>
__global__ __launch_bounds__(256)
void k_tc_gemm(int N, int K, const float* __restrict__ bias) {
    extern __shared__ __nv_bfloat16 smem[];
    const uint32_t sb = s2u(smem);
    const int tid = threadIdx.x, wid = tid >> 5, lane = tid & 31;
    const int nBase = blockIdx.x * 128, mBase = blockIdx.y * 128;
    const int KC = K >> 5;

    float* Cmat = (MODE == 0) ? g_qkv : (MODE == 1) ? g_xattn : (MODE == 2) ? g_h1 : g_h3;

    // per-thread copy slots: 8 chunks of 16B per stage
    int cs[8], cr[8], ct[8];
#pragma unroll
    for (int j = 0; j < 8; j++) {
        int s = tid + j * 256;          // 0..2047
        ct[j] = s >> 9;                 // tile 0..3
        cr[j] = (s >> 2) & 127;         // row
        cs[j] = s & 3;                  // chunk-of-4 within row
    }

    auto issue_stage = [&](int kc, int stg) {
#pragma unroll
        for (int j = 0; j < 8; j++) {
            int t = ct[j], r = cr[j], c4 = cs[j];
            const __nv_bfloat16* src =
                (t == 0) ? g_ahi : (t == 1) ? g_alo : (t == 2) ? g_whi : g_wlo;
            int rowg = ((t < 2) ? mBase : nBase) + r;
            const __nv_bfloat16* gp = src + (size_t)rowg * K + (kc << 5) + (c4 << 3);
            uint32_t dst = sb + (uint32_t)(stg * STG + t * TILE + r * TS + (c4 << 3)) * 2;
            CPA16(dst, gp);
        }
        CPA_COMMIT();
    };

    float acc[4][4][4];
#pragma unroll
    for (int mi = 0; mi < 4; mi++)
#pragma unroll
        for (int ni = 0; ni < 4; ni++)
#pragma unroll
            for (int c = 0; c < 4; c++) acc[mi][ni][c] = 0.f;

    const int m0 = (wid >> 2) * 64;
    const int n0 = (wid & 3) * 32;
    // ldmatrix lane address components
    const int arow = (lane & 15);
    const int akb  = (lane >> 4) * 8;
    const int l16  = lane & 15;
    const int brow = (l16 & 7);
    const int bkb  = (l16 >> 3) * 8;

    issue_stage(0, 0);

    for (int kc = 0; kc < KC; kc++) {
        const int stg = kc & 1;
        if (kc + 1 < KC) { issue_stage(kc + 1, stg ^ 1); CPA_WAIT1(); }
        else             { CPA_WAIT0(); }
        __syncthreads();

        const uint32_t base = sb + (uint32_t)(stg * STG) * 2;
        const uint32_t bAh = base;
        const uint32_t bAl = base + TILE * 2;
        const uint32_t bWh = base + 2 * TILE * 2;
        const uint32_t bWl = base + 3 * TILE * 2;

#pragma unroll
        for (int ks = 0; ks < 2; ks++) {
            const uint32_t ak = (uint32_t)(ks * 16 + akb) * 2;
            const uint32_t bk = (uint32_t)(ks * 16 + bkb) * 2;
            uint32_t ah[4][4], bh[4][2], bl[4][2];
#pragma unroll
            for (int mi = 0; mi < 4; mi++)
                ldmA(ah[mi], bAh + (uint32_t)((m0 + mi * 16 + arow) * TS) * 2 + ak);
#pragma unroll
            for (int ni = 0; ni < 4; ni++)
                ldmB(bh[ni], bWh + (uint32_t)((n0 + ni * 8 + brow) * TS) * 2 + bk);
#pragma unroll
            for (int mi = 0; mi < 4; mi++)
#pragma unroll
                for (int ni = 0; ni < 4; ni++) mma16816(acc[mi][ni], ah[mi], bh[ni]);
#pragma unroll
            for (int ni = 0; ni < 4; ni++)
                ldmB(bl[ni], bWl + (uint32_t)((n0 + ni * 8 + brow) * TS) * 2 + bk);
#pragma unroll
            for (int mi = 0; mi < 4; mi++)
#pragma unroll
                for (int ni = 0; ni < 4; ni++) mma16816(acc[mi][ni], ah[mi], bl[ni]);
#pragma unroll
            for (int mi = 0; mi < 4; mi++)
                ldmA(ah[mi], bAl + (uint32_t)((m0 + mi * 16 + arow) * TS) * 2 + ak);
#pragma unroll
            for (int mi = 0; mi < 4; mi++)
#pragma unroll
                for (int ni = 0; ni < 4; ni++) mma16816(acc[mi][ni], ah[mi], bh[ni]);
        }
        __syncthreads();
    }

    // epilogue
    const int gq = lane >> 2, gr = (lane & 3) * 2;
#pragma unroll
    for (int mi = 0; mi < 4; mi++) {
        int rowA = mBase + m0 + mi * 16 + gq;
#pragma unroll
        for (int ni = 0; ni < 4; ni++) {
            int col = nBase + n0 + ni * 8 + gr;
            float b0 = 0.f, b1 = 0.f;
            if (MODE == 1) { b0 = bias[col]; b1 = bias[col + 1]; }
            float2 v0 = make_float2(acc[mi][ni][0] + b0, acc[mi][ni][1] + b1);
            float2 v1 = make_float2(acc[mi][ni][2] + b0, acc[mi][ni][3] + b1);
            *(float2*)(Cmat + (size_t)rowA * N + col) = v0;
            *(float2*)(Cmat + (size_t)(rowA + 8) * N + col) = v1;
        }
    }
    (void)bias;
}

// ---------------- fused window attention ----------------
__global__ __launch_bounds__(256) void k_attn(const float* __restrict__ rpb) {
    __shared__ float qs[NWIN * HD];
    __shared__ float ks[NWIN * HD];
    __shared__ float vs[NWIN * HD];
    __shared__ float sc[NWIN * 50];
    __shared__ int   prow[NWIN];
    __shared__ int   lab [NWIN];

    const int bw = blockIdx.x;
    const int h  = blockIdx.y;
    const int tid = threadIdx.x;
    const int b = bw >> 2, w = bw & 3;

    if (tid < NWIN) {
        int rr = (w >> 1) * 7 + tid / 7;
        int cc = (w & 1) * 7 + tid % 7;
        prow[tid] = b * NPIX + ((rr + 3) % 14) * 14 + ((cc + 3) % 14);
        lab[tid]  = reg3(rr) * 3 + reg3(cc);
    }
    __syncthreads();

    for (int idx = tid; idx < NWIN * HD; idx += 256) {
        int t = idx >> 6, d = idx & 63;
        const float* base = g_qkv + (size_t)prow[t] * (3 * CC) + h * HD + d;
        qs[idx] = base[0];
        ks[idx] = base[CC];
        vs[idx] = base[2 * CC];
    }
    __syncthreads();

    for (int s = tid; s < NWIN * NWIN; s += 256) {
        int qi = s / NWIN, ki = s % NWIN;
        float a = 0.f;
#pragma unroll
        for (int d = 0; d < HD; d++) a += qs[qi * HD + d] * ks[ki * HD + d];
        a *= 0.125f;
        int qr = qi / 7, qc = qi % 7, kr = ki / 7, kc = ki % 7;
        int rpi = (qr - kr + 6) * 13 + (qc - kc + 6);
        a += rpb[rpi * HH + h];
        if (lab[qi] != lab[ki]) a -= 100.f;
        sc[qi * 50 + ki] = a;
    }
    __syncthreads();

    if (tid < NWIN) {
        float m = -1e30f;
        for (int k = 0; k < NWIN; k++) m = fmaxf(m, sc[tid * 50 + k]);
        float sum = 0.f;
        for (int k = 0; k < NWIN; k++) {
            float e = expf(sc[tid * 50 + k] - m);
            sc[tid * 50 + k] = e; sum += e;
        }
        float inv = 1.f / sum;
        for (int k = 0; k < NWIN; k++) sc[tid * 50 + k] *= inv;
    }
    __syncthreads();

    for (int idx = tid; idx < NWIN * HD; idx += 256) {
        int qi = idx >> 6, d = idx & 63;
        float a = 0.f;
#pragma unroll
        for (int k = 0; k < NWIN; k++) a += sc[qi * 50 + k] * vs[k * HD + d];
        g_attn[(size_t)prow[qi] * CC + h * HD + d] = a;
    }
}

// ---------------- BN stats (buffers selected inside device code) ----------------
__global__ void k_zero_stats() {
    int i = blockIdx.x * blockDim.x + threadIdx.x;
    if (i < HIDN) { g_s1[i] = 0.f; g_s2[i] = 0.f; }
}
template <int WHICH>
__global__ void k_colstats(int N) {
    const float* __restrict__ h = (WHICH == 0) ? g_h1 : (WHICH == 1) ? g_h2 : g_h3;
    int ch = blockIdx.x * 128 + threadIdx.x;
    int r0 = blockIdx.y * 128;
    float s = 0.f, q = 0.f;
    for (int r = 0; r < 128; r++) {
        float v = h[(size_t)(r0 + r) * N + ch];
        s += v; q += v * v;
    }
    atomicAdd(&g_s1[ch], s);
    atomicAdd(&g_s2[ch], q);
}
template <int WHICH>
__global__ void k_bn_hswish(int N, const float* __restrict__ g, const float* __restrict__ b) {
    float* h = (WHICH == 0) ? g_h1 : g_h2;
    int i = blockIdx.x * blockDim.x + threadIdx.x;
    if (i >= ROWS * (N / 4)) return;
    int c4 = (i % (N / 4)) * 4;
    float4 v = *(float4*)(h + (size_t)i * 4);
    float vv[4] = { v.x, v.y, v.z, v.w };
#pragma unroll
    for (int j = 0; j < 4; j++) {
        int ch = c4 + j;
        float m   = g_s1[ch] * (1.f / ROWS);
        float var = fmaxf(g_s2[ch] * (1.f / ROWS) - m * m, 0.f);
        float x = (vv[j] - m) * rsqrtf(var + 1e-5f) * g[ch] + b[ch];
        vv[j] = x * fminf(fmaxf(x + 3.f, 0.f), 6.f) * (1.f / 6.f);
    }
    *(float4*)(h + (size_t)i * 4) = make_float4(vv[0], vv[1], vv[2], vv[3]);
}

// ---------------- depthwise 3x3 (NHWC, zero 'SAME' padding) ----------------
__global__ void k_dwconv(const float* __restrict__ w) {
    int i = blockIdx.x * blockDim.x + threadIdx.x;
    if (i >= ROWS * (HIDN / 4)) return;
    int c4  = i % (HIDN / 4);
    int pix = i / (HIDN / 4);
    int b = pix / NPIX, p = pix % NPIX;
    int r = p / 14, c = p % 14;

    float wt[4][9];
#pragma unroll
    for (int j = 0; j < 4; j++)
#pragma unroll
        for (int t = 0; t < 9; t++) wt[j][t] = w[(size_t)(c4 * 4 + j) * 9 + t];

    float acc[4] = {0.f, 0.f, 0.f, 0.f};
#pragma unroll
    for (int dr = 0; dr < 3; dr++) {
        int rr = r + dr - 1;
        if (rr < 0 || rr > 13) continue;
#pragma unroll
        for (int dc = 0; dc < 3; dc++) {
            int cc = c + dc - 1;
            if (cc < 0 || cc > 13) continue;
            float4 v = *(const float4*)(g_h1 + ((size_t)(b * NPIX + rr * 14 + cc)) * HIDN + c4 * 4);
            acc[0] += v.x * wt[0][dr * 3 + dc];
            acc[1] += v.y * wt[1][dr * 3 + dc];
            acc[2] += v.z * wt[2][dr * 3 + dc];
            acc[3] += v.w * wt[3][dr * 3 + dc];
        }
    }
    *(float4*)(g_h2 + (size_t)i * 4) = make_float4(acc[0], acc[1], acc[2], acc[3]);
}

// ---------------- SE: pool + MLP ----------------
__global__ void k_sepool() {
    int b  = blockIdx.x;
    int ch = blockIdx.y * 128 + threadIdx.x;
    float s = 0.f;
    for (int p = 0; p < NPIX; p++) s += g_h2[((size_t)b * NPIX + p) * HIDN + ch];
    g_semean[b * HIDN + ch] = s * (1.f / NPIX);
}
__global__ __launch_bounds__(256) void k_semlp(
    const float* __restrict__ w1, const float* __restrict__ b1,
    const float* __restrict__ w2, const float* __restrict__ b2)
{
    __shared__ float sm[HIDN];
    __shared__ float hid[CC];
    int b = blockIdx.x, tid = threadIdx.x;
    for (int i = tid; i < HIDN; i += 256) sm[i] = g_semean[b * HIDN + i];
    __syncthreads();
    for (int j = tid; j < CC; j += 256) {
        float a = b1[j];
        const float* wr = w1 + (size_t)j * HIDN;
        for (int k = 0; k < HIDN; k += 4) {
            float4 wv = *(const float4*)(wr + k);
            a += wv.x * sm[k] + wv.y * sm[k + 1] + wv.z * sm[k + 2] + wv.w * sm[k + 3];
        }
        hid[j] = fmaxf(a, 0.f);
    }
    __syncthreads();
    for (int o = tid; o < HIDN; o += 256) {
        float a = b2[o];
        const float* wr = w2 + (size_t)o * CC;
        for (int k = 0; k < CC; k += 4) {
            float4 wv = *(const float4*)(wr + k);
            a += wv.x * hid[k] + wv.y * hid[k + 1] + wv.z * hid[k + 2] + wv.w * hid[k + 3];
        }
        g_sescale[b * HIDN + o] = fminf(fmaxf(a + 3.f, 0.f), 6.f) * (1.f / 6.f);
    }
}

// ---------------- final: bn3 + residual + write out ----------------
__global__ void k_final(const float* __restrict__ g, const float* __restrict__ bb,
                        float* __restrict__ out) {
    int i = blockIdx.x * blockDim.x + threadIdx.x;
    if (i >= ROWS * (CC / 4)) return;
    int c4  = (i % (CC / 4)) * 4;
    int pix = i / (CC / 4);
    int b = pix / NPIX, p = pix % NPIX;
    float4 hv = *(float4*)(g_h3 + (size_t)i * 4);
    float4 xv = *(float4*)(g_xattn + (size_t)i * 4);
    float h[4] = { hv.x, hv.y, hv.z, hv.w };
    float x[4] = { xv.x, xv.y, xv.z, xv.w };
#pragma unroll
    for (int j = 0; j < 4; j++) {
        int ch = c4 + j;
        float m   = g_s1[ch] * (1.f / ROWS);
        float var = fmaxf(g_s2[ch] * (1.f / ROWS) - m * m, 0.f);
        x[j] += (h[j] - m) * rsqrtf(var + 1e-5f) * g[ch] + bb[ch];
    }
    float* dst = out + ((size_t)b * 197 + 1 + p) * CC + c4;
    *(float4*)dst = make_float4(x[0], x[1], x[2], x[3]);
}

// ---------------- launch ----------------
extern "C" void kernel_launch(void* const* d_in, const int* in_sizes, int n_in,
                              void* d_out, int out_size) {
    int idx[18];
    for (int i = 0; i < 18; i++) idx[i] = i;
    const int X_ELEMS = BB * 197 * CC;
    if (n_in == 18 && in_sizes[0] != X_ELEMS && in_sizes[17] == X_ELEMS) {
        const int m[18] = {17, 16, 15, 0, 10, 8, 2, 1, 7, 4, 3, 13, 11, 14, 12, 9, 6, 5};
        for (int i = 0; i < 18; i++) idx[i] = m[i];
    }

    const float* x      = (const float*)d_in[idx[0]];
    const float* w_qkv  = (const float*)d_in[idx[1]];
    const float* w_proj = (const float*)d_in[idx[2]];
    const float* b_proj = (const float*)d_in[idx[3]];
    const float* rpb    = (const float*)d_in[idx[4]];
    const float* pw1_w  = (const float*)d_in[idx[5]];
    const float* bn1_g  = (const float*)d_in[idx[6]];
    const float* bn1_b  = (const float*)d_in[idx[7]];
    const float* dw_w   = (const float*)d_in[idx[8]];
    const float* bn2_g  = (const float*)d_in[idx[9]];
    const float* bn2_b  = (const float*)d_in[idx[10]];
    const float* se_w1  = (const float*)d_in[idx[11]];
    const float* se_b1  = (const float*)d_in[idx[12]];
    const float* se_w2  = (const float*)d_in[idx[13]];
    const float* se_b2  = (const float*)d_in[idx[14]];
    const float* pw2_w  = (const float*)d_in[idx[15]];
    const float* bn3_g  = (const float*)d_in[idx[16]];
    const float* bn3_b  = (const float*)d_in[idx[17]];
    float* out = (float*)d_out;

    cudaFuncSetAttribute(k_tc_gemm<0>, cudaFuncAttributeMaxDynamicSharedMemorySize, GSMEM);
    cudaFuncSetAttribute(k_tc_gemm<1>, cudaFuncAttributeMaxDynamicSharedMemorySize, GSMEM);
    cudaFuncSetAttribute(k_tc_gemm<2>, cudaFuncAttributeMaxDynamicSharedMemorySize, GSMEM);
    cudaFuncSetAttribute(k_tc_gemm<3>, cudaFuncAttributeMaxDynamicSharedMemorySize, GSMEM);

    k_cls<<<(BB * CC + 255) / 256, 256>>>(x, out);
    k_copyx<<<(ROWS * (CC / 4) + 255) / 256, 256>>>(x);

    // QKV
    k_cvt_a<0><<<(ROWS * CC + 255) / 256, 256>>>(CC);
    k_cvt_w<<<(3 * CC * CC + 255) / 256, 256>>>(w_qkv, 3 * CC * CC);
    k_tc_gemm<0><<<dim3(3 * CC / 128, ROWS / 128), 256, GSMEM>>>(3 * CC, CC, nullptr);

    k_attn<<<dim3(BB * 4, HH), 256>>>(rpb);

    // proj
    k_cvt_a<1><<<(ROWS * CC + 255) / 256, 256>>>(CC);
    k_cvt_w<<<(CC * CC + 255) / 256, 256>>>(w_proj, CC * CC);
    k_tc_gemm<1><<<dim3(CC / 128, ROWS / 128), 256, GSMEM>>>(CC, CC, b_proj);

    // pw1
    k_cvt_a<2><<<(ROWS * CC + 255) / 256, 256>>>(CC);
    k_cvt_w<<<(HIDN * CC + 255) / 256, 256>>>(pw1_w, HIDN * CC);
    k_tc_gemm<2><<<dim3(HIDN / 128, ROWS / 128), 256, GSMEM>>>(HIDN, CC, nullptr);

    k_zero_stats<<<(HIDN + 255) / 256, 256>>>();
    k_colstats<0><<<dim3(HIDN / 128, ROWS / 128), 128>>>(HIDN);
    k_bn_hswish<0><<<(ROWS * (HIDN / 4) + 255) / 256, 256>>>(HIDN, bn1_g, bn1_b);

    k_dwconv<<<(ROWS * (HIDN / 4) + 255) / 256, 256>>>(dw_w);
    k_zero_stats<<<(HIDN + 255) / 256, 256>>>();
    k_colstats<1><<<dim3(HIDN / 128, ROWS / 128), 128>>>(HIDN);
    k_bn_hswish<1><<<(ROWS * (HIDN / 4) + 255) / 256, 256>>>(HIDN, bn2_g, bn2_b);

    k_sepool<<<dim3(BB, HIDN / 128), 128>>>();
    k_semlp<<<BB, 256>>>(se_w1, se_b1, se_w2, se_b2);

    // pw2 (SE scale folded into conversion)
    k_cvt_a_se<<<(int)(((size_t)ROWS * HIDN + 255) / 256), 256>>>();
    k_cvt_w<<<(CC * HIDN + 255) / 256, 256>>>(pw2_w, CC * HIDN);
    k_tc_gemm<3><<<dim3(CC / 128, ROWS / 128), 256, GSMEM>>>(CC, HIDN, nullptr);

    k_zero_stats<<<(HIDN + 255) / 256, 256>>>();
    k_colstats<2><<<dim3(CC / 128, ROWS / 128), 128>>>(CC);
    k_final<<<(ROWS * (CC / 4) + 255) / 256, 256>>>(bn3_g, bn3_b, out);
    (void)in_sizes; (void)n_in; (void)out_size;
}

// round 11
// speedup vs baseline: 1.7912x; 1.1617x over previous
#include <cuda_runtime.h>
#include <cuda_bf16.h>
#include <cstdint>

// ---------------- problem constants ----------------
#define BB    32
#define PP    14
#define CC    768
#define HH    12
#define HD    64
#define HIDN  3072
#define NWIN  49
#define NPIX  196
#define ROWS  6272         // 32*196

// ---------------- scratch ----------------
__device__ float g_qkv  [(size_t)ROWS * 3 * CC];
__device__ float g_xattn[(size_t)ROWS * CC];
__device__ float g_h1   [(size_t)ROWS * HIDN];
__device__ float g_h2   [(size_t)ROWS * HIDN];
__device__ float g_h3   [(size_t)ROWS * CC];
__device__ float g_s1   [HIDN];
__device__ float g_s2   [HIDN];
__device__ float g_semean [BB * HIDN];
__device__ float g_sescale[BB * HIDN];
__device__ float g_bnsc [HIDN];
__device__ float g_bnsh [HIDN];
// bf16 split buffers
__device__ __nv_bfloat16 g_ahi[(size_t)ROWS * HIDN];
__device__ __nv_bfloat16 g_alo[(size_t)ROWS * HIDN];
__device__ __nv_bfloat16 g_bhi[(size_t)ROWS * CC];
__device__ __nv_bfloat16 g_blo[(size_t)ROWS * CC];
__device__ __nv_bfloat16 g_whi[(size_t)HIDN * CC];
__device__ __nv_bfloat16 g_wlo[(size_t)HIDN * CC];

__device__ __forceinline__ int reg3(int r) { return r < 7 ? 0 : (r < 11 ? 1 : 2); }
__device__ __forceinline__ float hsw(float x) { return x * __saturatef((x + 3.f) * (1.f / 6.f)); }
__device__ __forceinline__ void split2(float a, float b, uint32_t& hi, uint32_t& lo) {
    __nv_bfloat16 ha = __float2bfloat16(a), hb = __float2bfloat16(b);
    __nv_bfloat16 la = __float2bfloat16(a - __bfloat162float(ha));
    __nv_bfloat16 lb = __float2bfloat16(b - __bfloat162float(hb));
    __nv_bfloat162 H = __halves2bfloat162(ha, hb), L = __halves2bfloat162(la, lb);
    hi = *(uint32_t*)&H; lo = *(uint32_t*)&L;
}
__device__ __forceinline__ uint32_t s2u(const void* p) {
    uint32_t a;
    asm("{ .reg .u64 t; cvta.to.shared.u64 t, %1; cvt.u32.u64 %0, t; }" : "=r"(a) : "l"(p));
    return a;
}
#define CPA16(dst, src) asm volatile("cp.async.cg.shared.global [%0], [%1], 16;" :: "r"(dst), "l"(src) : "memory")
#define CPA_COMMIT()    asm volatile("cp.async.commit_group;" ::: "memory")
#define CPA_WAIT1()     asm volatile("cp.async.wait_group 1;" ::: "memory")
#define CPA_WAIT0()     asm volatile("cp.async.wait_group 0;" ::: "memory")

__device__ __forceinline__ void ldmA(uint32_t* r, uint32_t addr) {
    asm volatile("ldmatrix.sync.aligned.m8n8.x4.shared.b16 {%0,%1,%2,%3}, [%4];"
                 : "=r"(r[0]), "=r"(r[1]), "=r"(r[2]), "=r"(r[3]) : "r"(addr));
}
__device__ __forceinline__ void ldmB(uint32_t* r, uint32_t addr) {
    asm volatile("ldmatrix.sync.aligned.m8n8.x2.shared.b16 {%0,%1}, [%2];"
                 : "=r"(r[0]), "=r"(r[1]) : "r"(addr));
}
__device__ __forceinline__ void mma16816(float* c, const uint32_t* a, const uint32_t* b) {
    asm volatile("mma.sync.aligned.m16n8k16.row.col.f32.bf16.bf16.f32 "
                 "{%0,%1,%2,%3}, {%4,%5,%6,%7}, {%8,%9}, {%0,%1,%2,%3};"
                 : "+f"(c[0]), "+f"(c[1]), "+f"(c[2]), "+f"(c[3])
                 : "r"(a[0]), "r"(a[1]), "r"(a[2]), "r"(a[3]), "r"(b[0]), "r"(b[1]));
}

// ---------------- cls passthrough ----------------
__global__ void k_cls(const float* __restrict__ x, float* __restrict__ out) {
    int i = blockIdx.x * blockDim.x + threadIdx.x;
    if (i >= BB * CC) return;
    int b = i / CC, c = i % CC;
    out[(size_t)b * 197 * CC + c] = x[(size_t)b * 197 * CC + c];
}

// ---------------- copy pixel tokens, split to bf16 hi/lo ----------------
__global__ void k_copyx(const float* __restrict__ x) {
    int i = blockIdx.x * blockDim.x + threadIdx.x;
    if (i >= ROWS * (CC / 4)) return;
    int c4  = i % (CC / 4);
    int row = i / (CC / 4);
    int b = row / NPIX, p = row % NPIX;
    float4 v = *(const float4*)(x + ((size_t)b * 197 + 1 + p) * CC + c4 * 4);
    uint2 hi, lo;
    split2(v.x, v.y, hi.x, lo.x);
    split2(v.z, v.w, hi.y, lo.y);
    *(uint2*)(g_ahi + (size_t)row * CC + c4 * 4) = hi;
    *(uint2*)(g_alo + (size_t)row * CC + c4 * 4) = lo;
}

// ---------------- weight split (vectorized x4) ----------------
__global__ void k_cvt_w(const float* __restrict__ w, int total4) {
    int i = blockIdx.x * blockDim.x + threadIdx.x;
    if (i >= total4) return;
    float4 v = *(const float4*)(w + (size_t)i * 4);
    uint2 hi, lo;
    split2(v.x, v.y, hi.x, lo.x);
    split2(v.z, v.w, hi.y, lo.y);
    *(uint2*)(g_whi + (size_t)i * 4) = hi;
    *(uint2*)(g_wlo + (size_t)i * 4) = lo;
}

// ---------------- SE-scaled + BN2/hswish split (pw2 input) ----------------
__global__ void k_cvt_a_se() {
    int i = blockIdx.x * blockDim.x + threadIdx.x;
    if (i >= ROWS * (HIDN / 4)) return;
    int c4 = (i % (HIDN / 4)) * 4;
    int b  = i / (NPIX * (HIDN / 4));
    float4 v  = *(float4*)(g_h2 + (size_t)i * 4);
    float4 sc = *(float4*)(g_bnsc + c4);
    float4 sh = *(float4*)(g_bnsh + c4);
    float4 ss = *(float4*)(g_sescale + (size_t)b * HIDN + c4);
    float a0 = hsw(v.x * sc.x + sh.x) * ss.x;
    float a1 = hsw(v.y * sc.y + sh.y) * ss.y;
    float a2 = hsw(v.z * sc.z + sh.z) * ss.z;
    float a3 = hsw(v.w * sc.w + sh.w) * ss.w;
    uint2 hi, lo;
    split2(a0, a1, hi.x, lo.x);
    split2(a2, a3, hi.y, lo.y);
    *(uint2*)(g_ahi + (size_t)i * 4) = hi;
    *(uint2*)(g_alo + (size_t)i * 4) = lo;
}

// ---------------- HMMA GEMM: C[M,N] = A[M,K] @ W[N,K]^T (bf16 3-pass split) ---
// 128x128 CTA tile, BK=32, 8 warps (2x4), warp tile 64x32, 3-stage cp.async.
// MODE: 0:qkv 1:xattn(+bias, +split out) 2:h1 3:h3
#define TS   40
#define TILE (128 * TS)
#define STG  (4 * TILE)
#define GSMEM (3 * STG * 2)        // 122880 B

template <int MODE>
__global__ __launch_bounds__(256)
void k_tc_gemm(int N, int K, const float* __restrict__ bias) {
    extern __shared__ __nv_bfloat16 smem[];
    const uint32_t sb = s2u(smem);
    const int tid = threadIdx.x, wid = tid >> 5, lane = tid & 31;
    const int nBase = blockIdx.x * 128, mBase = blockIdx.y * 128;
    const int KC = K >> 5;

    const __nv_bfloat16* Ahi = (MODE == 1) ? g_bhi : g_ahi;
    const __nv_bfloat16* Alo = (MODE == 1) ? g_blo : g_alo;
    float* Cmat = (MODE == 0) ? g_qkv : (MODE == 1) ? g_xattn : (MODE == 2) ? g_h1 : g_h3;

    int cs[8], cr[8], ct[8];
#pragma unroll
    for (int j = 0; j < 8; j++) {
        int s = tid + j * 256;
        ct[j] = s >> 9;
        cr[j] = (s >> 2) & 127;
        cs[j] = s & 3;
    }

    auto issue_stage = [&](int kc, int stg) {
#pragma unroll
        for (int j = 0; j < 8; j++) {
            int t = ct[j], r = cr[j], c4 = cs[j];
            const __nv_bfloat16* src = (t == 0) ? Ahi : (t == 1) ? Alo : (t == 2) ? g_whi : g_wlo;
            int rowg = ((t < 2) ? mBase : nBase) + r;
            const __nv_bfloat16* gp = src + (size_t)rowg * K + (kc << 5) + (c4 << 3);
            uint32_t dst = sb + (uint32_t)(stg * STG + t * TILE + r * TS + (c4 << 3)) * 2;
            CPA16(dst, gp);
        }
        CPA_COMMIT();
    };

    float acc[4][4][4];
#pragma unroll
    for (int mi = 0; mi < 4; mi++)
#pragma unroll
        for (int ni = 0; ni < 4; ni++)
#pragma unroll
            for (int c = 0; c < 4; c++) acc[mi][ni][c] = 0.f;

    const int m0 = (wid >> 2) * 64;
    const int n0 = (wid & 3) * 32;
    const int arow = (lane & 15);
    const int akb  = (lane >> 4) * 8;
    const int l16  = lane & 15;
    const int brow = (l16 & 7);
    const int bkb  = (l16 >> 3) * 8;

    issue_stage(0, 0);
    if (KC > 1) issue_stage(1, 1);

    for (int kc = 0; kc < KC; kc++) {
        if (kc == KC - 1) { CPA_WAIT0(); } else { CPA_WAIT1(); }
        __syncthreads();
        if (kc + 2 < KC) issue_stage(kc + 2, (kc + 2) % 3);

        const uint32_t base = sb + (uint32_t)((kc % 3) * STG) * 2;
        const uint32_t bAh = base;
        const uint32_t bAl = base + TILE * 2;
        const uint32_t bWh = base + 2 * TILE * 2;
        const uint32_t bWl = base + 3 * TILE * 2;

#pragma unroll
        for (int ks = 0; ks < 2; ks++) {
            const uint32_t ak = (uint32_t)(ks * 16 + akb) * 2;
            const uint32_t bk = (uint32_t)(ks * 16 + bkb) * 2;
            uint32_t ah[4][4], al[4][4], bh[4][2], bl[4][2];
#pragma unroll
            for (int mi = 0; mi < 4; mi++)
                ldmA(ah[mi], bAh + (uint32_t)((m0 + mi * 16 + arow) * TS) * 2 + ak);
#pragma unroll
            for (int mi = 0; mi < 4; mi++)
                ldmA(al[mi], bAl + (uint32_t)((m0 + mi * 16 + arow) * TS) * 2 + ak);
#pragma unroll
            for (int ni = 0; ni < 4; ni++)
                ldmB(bh[ni], bWh + (uint32_t)((n0 + ni * 8 + brow) * TS) * 2 + bk);
#pragma unroll
            for (int ni = 0; ni < 4; ni++)
                ldmB(bl[ni], bWl + (uint32_t)((n0 + ni * 8 + brow) * TS) * 2 + bk);
#pragma unroll
            for (int mi = 0; mi < 4; mi++)
#pragma unroll
                for (int ni = 0; ni < 4; ni++) mma16816(acc[mi][ni], ah[mi], bh[ni]);
#pragma unroll
            for (int mi = 0; mi < 4; mi++)
#pragma unroll
                for (int ni = 0; ni < 4; ni++) mma16816(acc[mi][ni], ah[mi], bl[ni]);
#pragma unroll
            for (int mi = 0; mi < 4; mi++)
#pragma unroll
                for (int ni = 0; ni < 4; ni++) mma16816(acc[mi][ni], al[mi], bh[ni]);
        }
    }

    const int gq = lane >> 2, gr = (lane & 3) * 2;
#pragma unroll
    for (int mi = 0; mi < 4; mi++) {
        int rowA = mBase + m0 + mi * 16 + gq;
#pragma unroll
        for (int ni = 0; ni < 4; ni++) {
            int col = nBase + n0 + ni * 8 + gr;
            float b0 = 0.f, b1 = 0.f;
            if (MODE == 1) { b0 = bias[col]; b1 = bias[col + 1]; }
            float v00 = acc[mi][ni][0] + b0, v01 = acc[mi][ni][1] + b1;
            float v10 = acc[mi][ni][2] + b0, v11 = acc[mi][ni][3] + b1;
            *(float2*)(Cmat + (size_t)rowA * N + col) = make_float2(v00, v01);
            *(float2*)(Cmat + (size_t)(rowA + 8) * N + col) = make_float2(v10, v11);
            if (MODE == 1) {   // also emit split for pw1's A
                uint32_t hi, lo;
                split2(v00, v01, hi, lo);
                *(uint32_t*)(g_ahi + (size_t)rowA * N + col) = hi;
                *(uint32_t*)(g_alo + (size_t)rowA * N + col) = lo;
                split2(v10, v11, hi, lo);
                *(uint32_t*)(g_ahi + (size_t)(rowA + 8) * N + col) = hi;
                *(uint32_t*)(g_alo + (size_t)(rowA + 8) * N + col) = lo;
            }
        }
    }
    (void)bias;
}

// ---------------- fused window attention (register-tiled) ----------------
#define AT_ST 68
#define ATT_SMEM ((3 * NWIN * AT_ST + 50 * 50) * 4)
__global__ __launch_bounds__(256) void k_attn(const float* __restrict__ rpb) {
    extern __shared__ float asmem[];
    float* qs = asmem;                      // 49 x 68
    float* ks = qs + NWIN * AT_ST;
    float* vs = ks + NWIN * AT_ST;
    float* sc = vs + NWIN * AT_ST;          // 50 x 50
    __shared__ int prow[NWIN];
    __shared__ int lab [NWIN];

    const int bw = blockIdx.x;
    const int h  = blockIdx.y;
    const int tid = threadIdx.x;
    const int b = bw >> 2, w = bw & 3;

    if (tid < NWIN) {
        int rr = (w >> 1) * 7 + tid / 7;
        int cc = (w & 1) * 7 + tid % 7;
        prow[tid] = b * NPIX + ((rr + 3) % 14) * 14 + ((cc + 3) % 14);
        lab[tid]  = reg3(rr) * 3 + reg3(cc);
    }
    __syncthreads();

    for (int idx = tid; idx < NWIN * HD; idx += 256) {
        int t = idx >> 6, d = idx & 63;
        const float* base = g_qkv + (size_t)prow[t] * (3 * CC) + h * HD + d;
        qs[t * AT_ST + d] = base[0];
        ks[t * AT_ST + d] = base[CC];
        vs[t * AT_ST + d] = base[2 * CC];
    }
    __syncthreads();

    // QK^T: 13x13 tiles of 4x4 outputs (169 threads)
    if (tid < 169) {
        const int tq = (tid / 13) * 4, tk = (tid % 13) * 4;
        float a[4][4];
#pragma unroll
        for (int i = 0; i < 4; i++)
#pragma unroll
            for (int j = 0; j < 4; j++) a[i][j] = 0.f;
#pragma unroll
        for (int d4 = 0; d4 < 16; d4++) {
            float4 qv[4], kv[4];
#pragma unroll
            for (int j = 0; j < 4; j++) {
                qv[j] = *(float4*)&qs[min(tq + j, 48) * AT_ST + d4 * 4];
                kv[j] = *(float4*)&ks[min(tk + j, 48) * AT_ST + d4 * 4];
            }
#pragma unroll
            for (int i = 0; i < 4; i++)
#pragma unroll
                for (int j = 0; j < 4; j++)
                    a[i][j] += qv[i].x * kv[j].x + qv[i].y * kv[j].y
                             + qv[i].z * kv[j].z + qv[i].w * kv[j].w;
        }
#pragma unroll
        for (int i = 0; i < 4; i++) {
            int qi = tq + i;
            if (qi >= NWIN) break;
            int qr = qi / 7, qc = qi % 7;
#pragma unroll
            for (int j = 0; j < 4; j++) {
                int ki = tk + j;
                if (ki >= NWIN) continue;
                int kr = ki / 7, kc = ki % 7;
                float v = a[i][j] * 0.125f + rpb[((qr - kr + 6) * 13 + (qc - kc + 6)) * HH + h];
                if (lab[qi] != lab[ki]) v -= 100.f;
                sc[qi * 50 + ki] = v;
            }
        }
    }
    __syncthreads();

    if (tid < NWIN) {
        float m = -1e30f;
        for (int k = 0; k < NWIN; k++) m = fmaxf(m, sc[tid * 50 + k]);
        float sum = 0.f;
        for (int k = 0; k < NWIN; k++) {
            float e = expf(sc[tid * 50 + k] - m);
            sc[tid * 50 + k] = e; sum += e;
        }
        float inv = 1.f / sum;
        for (int k = 0; k < NWIN; k++) sc[tid * 50 + k] *= inv;
    }
    __syncthreads();

    // A @ V: 25 qi-pairs x 8 d8-tiles (200 threads); write split bf16 to g_bhi/g_blo
    if (tid < 200) {
        const int tq = (tid / 8) * 2, d8 = (tid % 8) * 8;
        float a0[8], a1[8];
#pragma unroll
        for (int j = 0; j < 8; j++) { a0[j] = 0.f; a1[j] = 0.f; }
        for (int k = 0; k < NWIN; k++) {
            float s0 = sc[tq * 50 + k];
            float s1 = sc[(tq + 1) * 50 + k];
            float4 va = *(float4*)&vs[k * AT_ST + d8];
            float4 vb = *(float4*)&vs[k * AT_ST + d8 + 4];
            a0[0] += s0 * va.x; a0[1] += s0 * va.y; a0[2] += s0 * va.z; a0[3] += s0 * va.w;
            a0[4] += s0 * vb.x; a0[5] += s0 * vb.y; a0[6] += s0 * vb.z; a0[7] += s0 * vb.w;
            a1[0] += s1 * va.x; a1[1] += s1 * va.y; a1[2] += s1 * va.z; a1[3] += s1 * va.w;
            a1[4] += s1 * vb.x; a1[5] += s1 * vb.y; a1[6] += s1 * vb.z; a1[7] += s1 * vb.w;
        }
#pragma unroll
        for (int r = 0; r < 2; r++) {
            int qi = tq + r;
            if (qi >= NWIN) continue;
            float* av = r ? a1 : a0;
            size_t off = (size_t)prow[qi] * CC + h * HD + d8;
#pragma unroll
            for (int j = 0; j < 4; j++) {
                uint32_t hi, lo;
                split2(av[2 * j], av[2 * j + 1], hi, lo);
                *(uint32_t*)(g_bhi + off + 2 * j) = hi;
                *(uint32_t*)(g_blo + off + 2 * j) = lo;
            }
        }
    }
}

// ---------------- BN stats ----------------
__global__ void k_zero_stats() {
    int i = blockIdx.x * blockDim.x + threadIdx.x;
    if (i < HIDN) { g_s1[i] = 0.f; g_s2[i] = 0.f; }
}
template <int WHICH>
__global__ void k_colstats(int N) {
    const float* __restrict__ h = (WHICH == 0) ? g_h1 : (WHICH == 1) ? g_h2 : g_h3;
    int ch = blockIdx.x * 128 + threadIdx.x;
    int r0 = blockIdx.y * 128;
    float s = 0.f, q = 0.f;
    for (int r = 0; r < 128; r++) {
        float v = h[(size_t)(r0 + r) * N + ch];
        s += v; q += v * v;
    }
    atomicAdd(&g_s1[ch], s);
    atomicAdd(&g_s2[ch], q);
}
__global__ void k_bnprep(const float* __restrict__ g, const float* __restrict__ b, int N) {
    int ch = blockIdx.x * blockDim.x + threadIdx.x;
    if (ch >= N) return;
    float m   = g_s1[ch] * (1.f / ROWS);
    float var = fmaxf(g_s2[ch] * (1.f / ROWS) - m * m, 0.f);
    float sc  = g[ch] * rsqrtf(var + 1e-5f);
    g_bnsc[ch] = sc;
    g_bnsh[ch] = b[ch] - m * sc;
}

// ---------------- depthwise 3x3 with fused BN1+hswish on input ----------------
__global__ void k_dwconv(const float* __restrict__ w) {
    int i = blockIdx.x * blockDim.x + threadIdx.x;
    if (i >= ROWS * (HIDN / 4)) return;
    int c4  = i % (HIDN / 4);
    int pix = i / (HIDN / 4);
    int b = pix / NPIX, p = pix % NPIX;
    int r = p / 14, c = p % 14;

    float4 sc = *(float4*)(g_bnsc + c4 * 4);
    float4 sh = *(float4*)(g_bnsh + c4 * 4);
    float wt[4][9];
#pragma unroll
    for (int j = 0; j < 4; j++)
#pragma unroll
        for (int t = 0; t < 9; t++) wt[j][t] = w[(size_t)(c4 * 4 + j) * 9 + t];

    float acc[4] = {0.f, 0.f, 0.f, 0.f};
#pragma unroll
    for (int dr = 0; dr < 3; dr++) {
        int rr = r + dr - 1;
        if (rr < 0 || rr > 13) continue;
#pragma unroll
        for (int dc = 0; dc < 3; dc++) {
            int cc = c + dc - 1;
            if (cc < 0 || cc > 13) continue;
            float4 v = *(const float4*)(g_h1 + ((size_t)(b * NPIX + rr * 14 + cc)) * HIDN + c4 * 4);
            float t0 = hsw(v.x * sc.x + sh.x);
            float t1 = hsw(v.y * sc.y + sh.y);
            float t2 = hsw(v.z * sc.z + sh.z);
            float t3 = hsw(v.w * sc.w + sh.w);
            acc[0] += t0 * wt[0][dr * 3 + dc];
            acc[1] += t1 * wt[1][dr * 3 + dc];
            acc[2] += t2 * wt[2][dr * 3 + dc];
            acc[3] += t3 * wt[3][dr * 3 + dc];
        }
    }
    *(float4*)(g_h2 + (size_t)i * 4) = make_float4(acc[0], acc[1], acc[2], acc[3]);
}

// ---------------- SE: pool (fused BN2+hswish) + MLP ----------------
__global__ void k_sepool() {
    int b  = blockIdx.x;
    int ch = blockIdx.y * 128 + threadIdx.x;
    float sc = g_bnsc[ch], sh = g_bnsh[ch];
    float s = 0.f;
    for (int p = 0; p < NPIX; p++)
        s += hsw(g_h2[((size_t)b * NPIX + p) * HIDN + ch] * sc + sh);
    g_semean[b * HIDN + ch] = s * (1.f / NPIX);
}
__global__ __launch_bounds__(256) void k_semlp(
    const float* __restrict__ w1, const float* __restrict__ b1,
    const float* __restrict__ w2, const float* __restrict__ b2)
{
    __shared__ float sm[HIDN];
    __shared__ float hid[CC];
    int b = blockIdx.x, tid = threadIdx.x;
    for (int i = tid; i < HIDN; i += 256) sm[i] = g_semean[b * HIDN + i];
    __syncthreads();
    for (int j = tid; j < CC; j += 256) {
        float a = b1[j];
        const float* wr = w1 + (size_t)j * HIDN;
        for (int k = 0; k < HIDN; k += 4) {
            float4 wv = *(const float4*)(wr + k);
            a += wv.x * sm[k] + wv.y * sm[k + 1] + wv.z * sm[k + 2] + wv.w * sm[k + 3];
        }
        hid[j] = fmaxf(a, 0.f);
    }
    __syncthreads();
    for (int o = tid; o < HIDN; o += 256) {
        float a = b2[o];
        const float* wr = w2 + (size_t)o * CC;
        for (int k = 0; k < CC; k += 4) {
            float4 wv = *(const float4*)(wr + k);
            a += wv.x * hid[k] + wv.y * hid[k + 1] + wv.z * hid[k + 2] + wv.w * hid[k + 3];
        }
        g_sescale[b * HIDN + o] = fminf(fmaxf(a + 3.f, 0.f), 6.f) * (1.f / 6.f);
    }
}

// ---------------- final: bn3 + residual + write out ----------------
__global__ void k_final(const float* __restrict__ g, const float* __restrict__ bb,
                        float* __restrict__ out) {
    int i = blockIdx.x * blockDim.x + threadIdx.x;
    if (i >= ROWS * (CC / 4)) return;
    int c4  = (i % (CC / 4)) * 4;
    int pix = i / (CC / 4);
    int b = pix / NPIX, p = pix % NPIX;
    float4 hv = *(float4*)(g_h3 + (size_t)i * 4);
    float4 xv = *(float4*)(g_xattn + (size_t)i * 4);
    float h[4] = { hv.x, hv.y, hv.z, hv.w };
    float x[4] = { xv.x, xv.y, xv.z, xv.w };
#pragma unroll
    for (int j = 0; j < 4; j++) {
        int ch = c4 + j;
        float m   = g_s1[ch] * (1.f / ROWS);
        float var = fmaxf(g_s2[ch] * (1.f / ROWS) - m * m, 0.f);
        x[j] += (h[j] - m) * rsqrtf(var + 1e-5f) * g[ch] + bb[ch];
    }
    float* dst = out + ((size_t)b * 197 + 1 + p) * CC + c4;
    *(float4*)dst = make_float4(x[0], x[1], x[2], x[3]);
}

// ---------------- launch ----------------
extern "C" void kernel_launch(void* const* d_in, const int* in_sizes, int n_in,
                              void* d_out, int out_size) {
    int idx[18];
    for (int i = 0; i < 18; i++) idx[i] = i;
    const int X_ELEMS = BB * 197 * CC;
    if (n_in == 18 && in_sizes[0] != X_ELEMS && in_sizes[17] == X_ELEMS) {
        const int m[18] = {17, 16, 15, 0, 10, 8, 2, 1, 7, 4, 3, 13, 11, 14, 12, 9, 6, 5};
        for (int i = 0; i < 18; i++) idx[i] = m[i];
    }

    const float* x      = (const float*)d_in[idx[0]];
    const float* w_qkv  = (const float*)d_in[idx[1]];
    const float* w_proj = (const float*)d_in[idx[2]];
    const float* b_proj = (const float*)d_in[idx[3]];
    const float* rpb    = (const float*)d_in[idx[4]];
    const float* pw1_w  = (const float*)d_in[idx[5]];
    const float* bn1_g  = (const float*)d_in[idx[6]];
    const float* bn1_b  = (const float*)d_in[idx[7]];
    const float* dw_w   = (const float*)d_in[idx[8]];
    const float* bn2_g  = (const float*)d_in[idx[9]];
    const float* bn2_b  = (const float*)d_in[idx[10]];
    const float* se_w1  = (const float*)d_in[idx[11]];
    const float* se_b1  = (const float*)d_in[idx[12]];
    const float* se_w2  = (const float*)d_in[idx[13]];
    const float* se_b2  = (const float*)d_in[idx[14]];
    const float* pw2_w  = (const float*)d_in[idx[15]];
    const float* bn3_g  = (const float*)d_in[idx[16]];
    const float* bn3_b  = (const float*)d_in[idx[17]];
    float* out = (float*)d_out;

    cudaFuncSetAttribute(k_tc_gemm<0>, cudaFuncAttributeMaxDynamicSharedMemorySize, GSMEM);
    cudaFuncSetAttribute(k_tc_gemm<1>, cudaFuncAttributeMaxDynamicSharedMemorySize, GSMEM);
    cudaFuncSetAttribute(k_tc_gemm<2>, cudaFuncAttributeMaxDynamicSharedMemorySize, GSMEM);
    cudaFuncSetAttribute(k_tc_gemm<3>, cudaFuncAttributeMaxDynamicSharedMemorySize, GSMEM);
    cudaFuncSetAttribute(k_attn, cudaFuncAttributeMaxDynamicSharedMemorySize, ATT_SMEM);

    k_cls<<<(BB * CC + 255) / 256, 256>>>(x, out);
    k_copyx<<<(ROWS * (CC / 4) + 255) / 256, 256>>>(x);

    // QKV
    k_cvt_w<<<(3 * CC * CC / 4 + 255) / 256, 256>>>(w_qkv, 3 * CC * CC / 4);
    k_tc_gemm<0><<<dim3(3 * CC / 128, ROWS / 128), 256, GSMEM>>>(3 * CC, CC, nullptr);

    k_attn<<<dim3(BB * 4, HH), 256, ATT_SMEM>>>(rpb);

    // proj (writes fp32 xattn + bf16 split for pw1)
    k_cvt_w<<<(CC * CC / 4 + 255) / 256, 256>>>(w_proj, CC * CC / 4);
    k_tc_gemm<1><<<dim3(CC / 128, ROWS / 128), 256, GSMEM>>>(CC, CC, b_proj);

    // pw1
    k_cvt_w<<<(HIDN * CC / 4 + 255) / 256, 256>>>(pw1_w, HIDN * CC / 4);
    k_tc_gemm<2><<<dim3(HIDN / 128, ROWS / 128), 256, GSMEM>>>(HIDN, CC, nullptr);

    // bn1 stats -> params (applied inside dwconv)
    k_zero_stats<<<(HIDN + 255) / 256, 256>>>();
    k_colstats<0><<<dim3(HIDN / 128, ROWS / 128), 128>>>(HIDN);
    k_bnprep<<<(HIDN + 255) / 256, 256>>>(bn1_g, bn1_b, HIDN);

    k_dwconv<<<(ROWS * (HIDN / 4) + 255) / 256, 256>>>(dw_w);

    // bn2 stats -> params (applied inside sepool / cvt_a_se)
    k_zero_stats<<<(HIDN + 255) / 256, 256>>>();
    k_colstats<1><<<dim3(HIDN / 128, ROWS / 128), 128>>>(HIDN);
    k_bnprep<<<(HIDN + 255) / 256, 256>>>(bn2_g, bn2_b, HIDN);

    k_sepool<<<dim3(BB, HIDN / 128), 128>>>();
    k_semlp<<<BB, 256>>>(se_w1, se_b1, se_w2, se_b2);

    // pw2
    k_cvt_a_se<<<(ROWS * (HIDN / 4) + 255) / 256, 256>>>();
    k_cvt_w<<<(CC * HIDN / 4 + 255) / 256, 256>>>(pw2_w, CC * HIDN / 4);
    k_tc_gemm<3><<<dim3(CC / 128, ROWS / 128), 256, GSMEM>>>(CC, HIDN, nullptr);

    k_zero_stats<<<(HIDN + 255) / 256, 256>>>();
    k_colstats<2><<<dim3(CC / 128, ROWS / 128), 128>>>(CC);
    k_final<<<(ROWS * (CC / 4) + 255) / 256, 256>>>(bn3_g, bn3_b, out);
    (void)in_sizes; (void)n_in; (void)out_size;
}